// round 1
// baseline (speedup 1.0000x reference)
#include <cuda_runtime.h>

// SpatialTransformer: 3D trilinear warp with dense displacement field.
// vol: [B=2, D=160, H=160, W=160, C=2] f32
// trf: [B,D,H,W,3] f32 (displacement in voxels, dims order (d,h,w))
// out: [B,D,H,W,C] f32
//
// Semantics (faithful to reference):
//   loc  = mesh + trf              (unclipped, float)
//   l0c  = clip(floor(loc), 0, dim-1)
//   l1c  = clip(l0c + 1,    0, dim-1)
//   d1   = l1c - loc   (weight for floor corner, uses UNCLIPPED loc)
//   d0   = 1 - d1      (weight for ceil corner)
//   out  = sum over 8 corners of (prod of per-dim weights) * vol[corner]

#define DIM 160
#define BD  320   // B * D

__global__ __launch_bounds__(DIM)
void st_warp_kernel(const float* __restrict__ vol,
                    const float* __restrict__ trf,
                    float* __restrict__ out)
{
    const int x  = threadIdx.x;        // 0..159 (W)
    const int y  = blockIdx.y;         // 0..159 (H)
    const int zb = blockIdx.x;         // 0..319 == b*D + z
    const int z  = zb & 0 ? 0 : (zb % DIM);   // zb % 160
    const int bD = zb - z;                     // b * D

    const int vox = (zb * DIM + y) * DIM + x;  // linear voxel index over B*D*H*W

    // displacement (dims order: d, h, w)
    const float tz = trf[vox * 3 + 0];
    const float ty = trf[vox * 3 + 1];
    const float tx = trf[vox * 3 + 2];

    const float lz = (float)z + tz;
    const float ly = (float)y + ty;
    const float lx = (float)x + tx;

    const float maxl = (float)(DIM - 1);

    const float z0f = fminf(fmaxf(floorf(lz), 0.0f), maxl);
    const float y0f = fminf(fmaxf(floorf(ly), 0.0f), maxl);
    const float x0f = fminf(fmaxf(floorf(lx), 0.0f), maxl);
    const float z1f = fminf(z0f + 1.0f, maxl);
    const float y1f = fminf(y0f + 1.0f, maxl);
    const float x1f = fminf(x0f + 1.0f, maxl);

    // weights: index 0 -> floor corner (d1), index 1 -> ceil corner (d0)
    const float wz0 = z1f - lz, wz1 = 1.0f - wz0;
    const float wy0 = y1f - ly, wy1 = 1.0f - wy0;
    const float wx0 = x1f - lx, wx1 = 1.0f - wx0;

    const int iz0 = (int)z0f, iz1 = (int)z1f;
    const int iy0 = (int)y0f, iy1 = (int)y1f;
    const int ix0 = (int)x0f, ix1 = (int)x1f;

    // vol viewed as float2 (C=2 contiguous): index = ((bD+zz)*H + yy)*W + xx
    const float2* __restrict__ v2 = (const float2*)vol;

    const int r00 = ((bD + iz0) * DIM + iy0) * DIM;
    const int r01 = ((bD + iz0) * DIM + iy1) * DIM;
    const int r10 = ((bD + iz1) * DIM + iy0) * DIM;
    const int r11 = ((bD + iz1) * DIM + iy1) * DIM;

    const float2 c000 = v2[r00 + ix0];
    const float2 c001 = v2[r00 + ix1];
    const float2 c010 = v2[r01 + ix0];
    const float2 c011 = v2[r01 + ix1];
    const float2 c100 = v2[r10 + ix0];
    const float2 c101 = v2[r10 + ix1];
    const float2 c110 = v2[r11 + ix0];
    const float2 c111 = v2[r11 + ix1];

    const float w000 = wz0 * wy0 * wx0;
    const float w001 = wz0 * wy0 * wx1;
    const float w010 = wz0 * wy1 * wx0;
    const float w011 = wz0 * wy1 * wx1;
    const float w100 = wz1 * wy0 * wx0;
    const float w101 = wz1 * wy0 * wx1;
    const float w110 = wz1 * wy1 * wx0;
    const float w111 = wz1 * wy1 * wx1;

    float o0 = w000 * c000.x;
    float o1 = w000 * c000.y;
    o0 = fmaf(w001, c001.x, o0);  o1 = fmaf(w001, c001.y, o1);
    o0 = fmaf(w010, c010.x, o0);  o1 = fmaf(w010, c010.y, o1);
    o0 = fmaf(w011, c011.x, o0);  o1 = fmaf(w011, c011.y, o1);
    o0 = fmaf(w100, c100.x, o0);  o1 = fmaf(w100, c100.y, o1);
    o0 = fmaf(w101, c101.x, o0);  o1 = fmaf(w101, c101.y, o1);
    o0 = fmaf(w110, c110.x, o0);  o1 = fmaf(w110, c110.y, o1);
    o0 = fmaf(w111, c111.x, o0);  o1 = fmaf(w111, c111.y, o1);

    ((float2*)out)[vox] = make_float2(o0, o1);
}

extern "C" void kernel_launch(void* const* d_in, const int* in_sizes, int n_in,
                              void* d_out, int out_size)
{
    const float* vol = (const float*)d_in[0];
    const float* trf = (const float*)d_in[1];
    float* out = (float*)d_out;

    dim3 grid(BD, DIM, 1);   // (b*D, H)
    dim3 block(DIM, 1, 1);   // W = 160 = 5 warps exactly
    st_warp_kernel<<<grid, block>>>(vol, trf, out);
}

// round 2
// speedup vs baseline: 1.1917x; 1.1917x over previous
#include <cuda_runtime.h>
#include <cuda_fp16.h>

// SpatialTransformer: 3D trilinear warp, dense displacement field.
// vol: [B=2, D=160, H=160, W=160, C=2] f32
// trf: [B,D,H,W,3] f32
// out: [B,D,H,W,C] f32
//
// Strategy: the kernel is L1tex-wavefront bound (8 scattered gathers/thread in R1).
// Prologue builds E2[z][y][x] = 2x2 (y,x)-corner block in fp16:
//   { v[y][x], v[y][x+1c], v[y+1c][x], v[y+1c][x+1c] }  (clipping baked in)
// packed as one uint4 (16B). Main kernel then does only 2 gather LDG.128
// (one per z corner) instead of 8 LDG.64.
// Weights are computed in f32 exactly as the reference:
//   l0c = clip(floor(loc),0,159); l1c = clip(l0c+1,0,159)
//   d1  = l1c - loc (floor weight, UNCLIPPED loc); d0 = 1 - d1

#define DIM  160
#define BD   320                 // B * D
#define SLAB (DIM * DIM)         // 25600
#define NVOX (BD * DIM * DIM)    // 8,192,000

// 131 MB scratch: corner-block volume (zero-init BSS, no runtime allocation)
__device__ uint4 g_E2[NVOX];

static __device__ __forceinline__ unsigned pack_h2(float a, float b) {
    __half2 h = __floats2half2_rn(a, b);
    return *reinterpret_cast<unsigned*>(&h);
}

__global__ __launch_bounds__(DIM)
void build_E2_kernel(const float* __restrict__ vol)
{
    const int x  = threadIdx.x;       // W
    const int y  = blockIdx.y;        // H
    const int zb = blockIdx.x;        // b*D + z
    const int xp = min(x + 1, DIM - 1);
    const int yp = min(y + 1, DIM - 1);

    const float2* __restrict__ v2 = (const float2*)vol;
    const int base = zb * SLAB;

    const float2 a = v2[base + y  * DIM + x ];  // (y0,x0)
    const float2 b = v2[base + y  * DIM + xp];  // (y0,x1)
    const float2 c = v2[base + yp * DIM + x ];  // (y1,x0)
    const float2 d = v2[base + yp * DIM + xp];  // (y1,x1)

    uint4 e;
    e.x = pack_h2(a.x, a.y);
    e.y = pack_h2(b.x, b.y);
    e.z = pack_h2(c.x, c.y);
    e.w = pack_h2(d.x, d.y);
    g_E2[base + y * DIM + x] = e;
}

static __device__ __forceinline__ float2 h2f(unsigned u) {
    __half2 h = *reinterpret_cast<__half2*>(&u);
    return __half22float2(h);
}

__global__ __launch_bounds__(DIM)
void st_warp_kernel(const float* __restrict__ trf,
                    float* __restrict__ out)
{
    const int x  = threadIdx.x;       // 0..159 (W)
    const int y  = blockIdx.y;        // 0..159 (H)
    const int zb = blockIdx.x;        // 0..319 == b*D + z
    const int z  = zb % DIM;
    const int bD = zb - z;            // b * D

    const int vox = (zb * DIM + y) * DIM + x;

    const float tz = trf[vox * 3 + 0];
    const float ty = trf[vox * 3 + 1];
    const float tx = trf[vox * 3 + 2];

    const float lz = (float)z + tz;
    const float ly = (float)y + ty;
    const float lx = (float)x + tx;

    const float maxl = (float)(DIM - 1);

    const float z0f = fminf(fmaxf(floorf(lz), 0.0f), maxl);
    const float y0f = fminf(fmaxf(floorf(ly), 0.0f), maxl);
    const float x0f = fminf(fmaxf(floorf(lx), 0.0f), maxl);
    const float z1f = fminf(z0f + 1.0f, maxl);
    const float y1f = fminf(y0f + 1.0f, maxl);
    const float x1f = fminf(x0f + 1.0f, maxl);

    // per-dim weights: w?0 pairs with the floor corner, w?1 with the ceil
    const float wz0 = z1f - lz, wz1 = 1.0f - wz0;
    const float wy0 = y1f - ly, wy1 = 1.0f - wy0;
    const float wx0 = x1f - lx, wx1 = 1.0f - wx0;

    const int iz0 = (int)z0f, iz1 = (int)z1f;
    const int iy0 = (int)y0f;
    const int ix0 = (int)x0f;

    // 2x2 (y,x) corner blocks at the two z corners: 2 gathers total
    const int e_idx = iy0 * DIM + ix0;
    const uint4 eA = g_E2[(bD + iz0) * SLAB + e_idx];   // z0 plane
    const uint4 eB = g_E2[(bD + iz1) * SLAB + e_idx];   // z1 plane

    const float w00 = wy0 * wx0;   // (y0,x0)
    const float w01 = wy0 * wx1;   // (y0,x1)
    const float w10 = wy1 * wx0;   // (y1,x0)
    const float w11 = wy1 * wx1;   // (y1,x1)

    const float2 a00 = h2f(eA.x), a01 = h2f(eA.y), a10 = h2f(eA.z), a11 = h2f(eA.w);
    const float2 b00 = h2f(eB.x), b01 = h2f(eB.y), b10 = h2f(eB.z), b11 = h2f(eB.w);

    // bilinear in (y,x) at each z plane, then linear in z
    float p0 = w00 * a00.x;
    float p1 = w00 * a00.y;
    p0 = fmaf(w01, a01.x, p0);  p1 = fmaf(w01, a01.y, p1);
    p0 = fmaf(w10, a10.x, p0);  p1 = fmaf(w10, a10.y, p1);
    p0 = fmaf(w11, a11.x, p0);  p1 = fmaf(w11, a11.y, p1);

    float q0 = w00 * b00.x;
    float q1 = w00 * b00.y;
    q0 = fmaf(w01, b01.x, q0);  q1 = fmaf(w01, b01.y, q1);
    q0 = fmaf(w10, b10.x, q0);  q1 = fmaf(w10, b10.y, q1);
    q0 = fmaf(w11, b11.x, q0);  q1 = fmaf(w11, b11.y, q1);

    const float o0 = wz0 * p0 + wz1 * q0;
    const float o1 = wz0 * p1 + wz1 * q1;

    ((float2*)out)[vox] = make_float2(o0, o1);
}

extern "C" void kernel_launch(void* const* d_in, const int* in_sizes, int n_in,
                              void* d_out, int out_size)
{
    const float* vol = (const float*)d_in[0];
    const float* trf = (const float*)d_in[1];
    float* out = (float*)d_out;

    dim3 grid(BD, DIM, 1);    // (b*D, H)
    dim3 block(DIM, 1, 1);    // W = 160 threads = 5 warps

    build_E2_kernel<<<grid, block>>>(vol);
    st_warp_kernel<<<grid, block>>>(trf, out);
}

// round 3
// speedup vs baseline: 1.2421x; 1.0423x over previous
#include <cuda_runtime.h>
#include <cuda_fp16.h>

// SpatialTransformer: 3D trilinear warp, dense displacement field.
// vol: [B=2, D=160, H=160, W=160, C=2] f32, trf: [B,D,H,W,3] f32 -> out like vol.
//
// R2 scheme: prologue builds E2[z][y][x] = 2x2 (y,x)-corner block in fp16
// (clipping baked in), one uint4 each; main kernel does 2 gather LDG.128.
// R3: both kernels process 2 voxels/thread (rows y and y+80) to double MLP —
// main kernel was latency-exposed (issue 28%, L1 73%, DRAM 45%).

#define DIM  160
#define HALF 80
#define BD   320                 // B * D
#define SLAB (DIM * DIM)         // 25600
#define NVOX (BD * DIM * DIM)    // 8,192,000

// 131 MB scratch: corner-block volume (device global, no runtime allocation)
__device__ uint4 g_E2[NVOX];

static __device__ __forceinline__ unsigned pack_h2(float a, float b) {
    __half2 h = __floats2half2_rn(a, b);
    return *reinterpret_cast<unsigned*>(&h);
}
static __device__ __forceinline__ float2 h2f(unsigned u) {
    __half2 h = *reinterpret_cast<__half2*>(&u);
    return __half22float2(h);
}

__global__ __launch_bounds__(DIM)
void build_E2_kernel(const float* __restrict__ vol)
{
    const int x  = threadIdx.x;       // W
    const int y0 = blockIdx.y;        // H row A (0..79)
    const int zb = blockIdx.x;        // b*D + z
    const int xp = min(x + 1, DIM - 1);
    const int base = zb * SLAB;
    const float2* __restrict__ v2 = (const float2*)vol;

    #pragma unroll
    for (int h = 0; h < 2; h++) {
        const int y  = y0 + h * HALF;
        const int yp = min(y + 1, DIM - 1);
        const float2 a = v2[base + y  * DIM + x ];
        const float2 b = v2[base + y  * DIM + xp];
        const float2 c = v2[base + yp * DIM + x ];
        const float2 d = v2[base + yp * DIM + xp];
        uint4 e;
        e.x = pack_h2(a.x, a.y);
        e.y = pack_h2(b.x, b.y);
        e.z = pack_h2(c.x, c.y);
        e.w = pack_h2(d.x, d.y);
        g_E2[base + y * DIM + x] = e;
    }
}

__global__ __launch_bounds__(DIM)
void st_warp_kernel(const float* __restrict__ trf,
                    float* __restrict__ out)
{
    const int x  = threadIdx.x;       // 0..159 (W)
    const int y0 = blockIdx.y;        // 0..79
    const int zb = blockIdx.x;        // 0..319 == b*D + z
    const int z  = (zb >= DIM) ? (zb - DIM) : zb;
    const int bD = zb - z;            // b * D
    const float maxl = (float)(DIM - 1);

    const int voxA = (zb * DIM + y0) * DIM + x;
    const int voxB = voxA + HALF * DIM;

    // issue all 6 trf loads up front (independent)
    const float tzA = trf[voxA * 3 + 0];
    const float tyA = trf[voxA * 3 + 1];
    const float txA = trf[voxA * 3 + 2];
    const float tzB = trf[voxB * 3 + 0];
    const float tyB = trf[voxB * 3 + 1];
    const float txB = trf[voxB * 3 + 2];

    // ---- voxel A indices/weights ----
    const float lzA = (float)z + tzA;
    const float lyA = (float)y0 + tyA;
    const float lxA = (float)x + txA;
    const float z0A = fminf(fmaxf(floorf(lzA), 0.0f), maxl);
    const float y0A = fminf(fmaxf(floorf(lyA), 0.0f), maxl);
    const float x0A = fminf(fmaxf(floorf(lxA), 0.0f), maxl);
    const float z1A = fminf(z0A + 1.0f, maxl);
    const float y1A = fminf(y0A + 1.0f, maxl);
    const float x1A = fminf(x0A + 1.0f, maxl);
    const float wzA0 = z1A - lzA, wzA1 = 1.0f - wzA0;
    const float wyA0 = y1A - lyA, wyA1 = 1.0f - wyA0;
    const float wxA0 = x1A - lxA, wxA1 = 1.0f - wxA0;
    const int eiA = (int)y0A * DIM + (int)x0A;

    // ---- voxel B indices/weights ----
    const float lzB = (float)z + tzB;
    const float lyB = (float)(y0 + HALF) + tyB;
    const float lxB = (float)x + txB;
    const float z0B = fminf(fmaxf(floorf(lzB), 0.0f), maxl);
    const float y0B = fminf(fmaxf(floorf(lyB), 0.0f), maxl);
    const float x0B = fminf(fmaxf(floorf(lxB), 0.0f), maxl);
    const float z1B = fminf(z0B + 1.0f, maxl);
    const float y1B = fminf(y0B + 1.0f, maxl);
    const float x1B = fminf(x0B + 1.0f, maxl);
    const float wzB0 = z1B - lzB, wzB1 = 1.0f - wzB0;
    const float wyB0 = y1B - lyB, wyB1 = 1.0f - wyB0;
    const float wxB0 = x1B - lxB, wxB1 = 1.0f - wxB0;
    const int eiB = (int)y0B * DIM + (int)x0B;

    // ---- 4 independent gathers in flight ----
    const uint4 eA0 = g_E2[(bD + (int)z0A) * SLAB + eiA];
    const uint4 eA1 = g_E2[(bD + (int)z1A) * SLAB + eiA];
    const uint4 eB0 = g_E2[(bD + (int)z0B) * SLAB + eiB];
    const uint4 eB1 = g_E2[(bD + (int)z1B) * SLAB + eiB];

    // ---- voxel A interpolation ----
    {
        const float w00 = wyA0 * wxA0, w01 = wyA0 * wxA1;
        const float w10 = wyA1 * wxA0, w11 = wyA1 * wxA1;
        const float2 a00 = h2f(eA0.x), a01 = h2f(eA0.y), a10 = h2f(eA0.z), a11 = h2f(eA0.w);
        const float2 b00 = h2f(eA1.x), b01 = h2f(eA1.y), b10 = h2f(eA1.z), b11 = h2f(eA1.w);
        float p0 = w00 * a00.x, p1 = w00 * a00.y;
        p0 = fmaf(w01, a01.x, p0);  p1 = fmaf(w01, a01.y, p1);
        p0 = fmaf(w10, a10.x, p0);  p1 = fmaf(w10, a10.y, p1);
        p0 = fmaf(w11, a11.x, p0);  p1 = fmaf(w11, a11.y, p1);
        float q0 = w00 * b00.x, q1 = w00 * b00.y;
        q0 = fmaf(w01, b01.x, q0);  q1 = fmaf(w01, b01.y, q1);
        q0 = fmaf(w10, b10.x, q0);  q1 = fmaf(w10, b10.y, q1);
        q0 = fmaf(w11, b11.x, q0);  q1 = fmaf(w11, b11.y, q1);
        ((float2*)out)[voxA] = make_float2(wzA0 * p0 + wzA1 * q0,
                                           wzA0 * p1 + wzA1 * q1);
    }
    // ---- voxel B interpolation ----
    {
        const float w00 = wyB0 * wxB0, w01 = wyB0 * wxB1;
        const float w10 = wyB1 * wxB0, w11 = wyB1 * wxB1;
        const float2 a00 = h2f(eB0.x), a01 = h2f(eB0.y), a10 = h2f(eB0.z), a11 = h2f(eB0.w);
        const float2 b00 = h2f(eB1.x), b01 = h2f(eB1.y), b10 = h2f(eB1.z), b11 = h2f(eB1.w);
        float p0 = w00 * a00.x, p1 = w00 * a00.y;
        p0 = fmaf(w01, a01.x, p0);  p1 = fmaf(w01, a01.y, p1);
        p0 = fmaf(w10, a10.x, p0);  p1 = fmaf(w10, a10.y, p1);
        p0 = fmaf(w11, a11.x, p0);  p1 = fmaf(w11, a11.y, p1);
        float q0 = w00 * b00.x, q1 = w00 * b00.y;
        q0 = fmaf(w01, b01.x, q0);  q1 = fmaf(w01, b01.y, q1);
        q0 = fmaf(w10, b10.x, q0);  q1 = fmaf(w10, b10.y, q1);
        q0 = fmaf(w11, b11.x, q0);  q1 = fmaf(w11, b11.y, q1);
        ((float2*)out)[voxB] = make_float2(wzB0 * p0 + wzB1 * q0,
                                           wzB0 * p1 + wzB1 * q1);
    }
}

extern "C" void kernel_launch(void* const* d_in, const int* in_sizes, int n_in,
                              void* d_out, int out_size)
{
    const float* vol = (const float*)d_in[0];
    const float* trf = (const float*)d_in[1];
    float* out = (float*)d_out;

    dim3 grid(BD, HALF, 1);   // (b*D, H/2) — 2 rows per block
    dim3 block(DIM, 1, 1);    // W = 160 threads = 5 warps

    build_E2_kernel<<<grid, block>>>(vol);
    st_warp_kernel<<<grid, block>>>(trf, out);
}